// round 11
// baseline (speedup 1.0000x reference)
#include <cuda_runtime.h>
#include <cuda_bf16.h>
#include <cstdint>

// ---------------- problem constants ----------------
#define D_    768
#define H_    3072
#define E_    8
#define MAXPE 4096
#define NMAX  4096

#define BM 128
#define BN 256
#define BK 32

typedef unsigned short u16;

// ---------------- device scratch (bf16 hi/lo planes) ----------------
__device__ u16   g_xhi[(size_t)NMAX * D_];
__device__ u16   g_xlo[(size_t)NMAX * D_];
__device__ u16   g_wfchi[(size_t)E_ * H_ * D_];
__device__ u16   g_wfclo[(size_t)E_ * H_ * D_];
__device__ u16   g_wprohi[(size_t)E_ * D_ * H_];
__device__ u16   g_wprolo[(size_t)E_ * D_ * H_];
__device__ u16   g_hhi[(size_t)E_ * MAXPE * H_];
__device__ u16   g_hlo[(size_t)E_ * MAXPE * H_];
__device__ int   g_tok[E_ * MAXPE];
__device__ float g_wt[E_ * MAXPE];
__device__ float g_probs[(size_t)NMAX * E_];
__device__ int   g_cnt[E_];
__device__ float g_sumprob[E_];

// ---------------- helpers ----------------
__device__ __forceinline__ uint32_t smem_u32(const void* p) {
    uint32_t a;
    asm("{ .reg .u64 t; cvta.to.shared.u64 t, %1; cvt.u32.u64 %0, t; }" : "=r"(a) : "l"(p));
    return a;
}
__device__ __forceinline__ void ldsm4(uint32_t* r, uint32_t addr) {
    asm volatile("ldmatrix.sync.aligned.m8n8.x4.shared.b16 {%0,%1,%2,%3}, [%4];"
                 : "=r"(r[0]), "=r"(r[1]), "=r"(r[2]), "=r"(r[3]) : "r"(addr));
}
__device__ __forceinline__ void mma_bf16(float* c, const uint32_t* a, uint32_t b0, uint32_t b1) {
    asm volatile("mma.sync.aligned.m16n8k16.row.col.f32.bf16.bf16.f32 "
                 "{%0,%1,%2,%3}, {%4,%5,%6,%7}, {%8,%9}, {%0,%1,%2,%3};"
                 : "+f"(c[0]), "+f"(c[1]), "+f"(c[2]), "+f"(c[3])
                 : "r"(a[0]), "r"(a[1]), "r"(a[2]), "r"(a[3]), "r"(b0), "r"(b1));
}
__device__ __forceinline__ void cpa16(uint32_t dst, const void* src) {
    asm volatile("cp.async.cg.shared.global [%0], [%1], 16;" :: "r"(dst), "l"(src));
}
__device__ __forceinline__ void cp_commit() {
    asm volatile("cp.async.commit_group;" ::: "memory");
}
__device__ __forceinline__ void cp_wait1() {
    asm volatile("cp.async.wait_group 1;" ::: "memory");
}
// split two floats -> hi bf16x2 (packed) and lo bf16x2 (packed)
__device__ __forceinline__ void split2(float x, float y, uint32_t& h, uint32_t& l) {
    __nv_bfloat162 a = __floats2bfloat162_rn(x, y);
    h = *reinterpret_cast<uint32_t*>(&a);
    float f0 = __uint_as_float(h << 16);
    float f1 = __uint_as_float(h & 0xffff0000u);
    __nv_bfloat162 b = __floats2bfloat162_rn(x - f0, y - f1);
    l = *reinterpret_cast<uint32_t*>(&b);
}

// ---------------- kernel: fp32 -> bf16 hi/lo planes ----------------
__global__ void cvt_kernel(const float* __restrict__ src, u16* __restrict__ hi,
                           u16* __restrict__ lo, int n4) {
    for (int i = blockIdx.x * blockDim.x + threadIdx.x; i < n4;
         i += gridDim.x * blockDim.x) {
        float4 v = ((const float4*)src)[i];
        uint32_t h0, h1, l0, l1;
        split2(v.x, v.y, h0, l0);
        split2(v.z, v.w, h1, l1);
        ((uint2*)hi)[i] = make_uint2(h0, h1);
        ((uint2*)lo)[i] = make_uint2(l0, l1);
    }
}

// ---------------- kernel 0: zero output + counters ----------------
__global__ void zero_kernel(float* __restrict__ out, int out_size) {
    for (int i = blockIdx.x * blockDim.x + threadIdx.x; i < out_size;
         i += gridDim.x * blockDim.x)
        out[i] = 0.0f;
    if (blockIdx.x == 0 && threadIdx.x < E_) g_cnt[threadIdx.x] = 0;
}

// ---------------- kernel 1: gating ----------------
__global__ __launch_bounds__(256) void gate_kernel(const float* __restrict__ x,
                                                   const float* __restrict__ gw,
                                                   int N) {
    int token = blockIdx.x * 8 + (threadIdx.x >> 5);
    int lane  = threadIdx.x & 31;
    if (token >= N) return;

    const float* xr = x + (size_t)token * D_;
    float xs[D_ / 32];
#pragma unroll
    for (int i = 0; i < D_ / 32; i++) xs[i] = xr[lane + i * 32];

    float p[E_];
#pragma unroll
    for (int e = 0; e < E_; e++) {
        const float* g = gw + e * D_;
        float s = 0.0f;
#pragma unroll
        for (int i = 0; i < D_ / 32; i++) s += xs[i] * g[lane + i * 32];
#pragma unroll
        for (int o = 16; o; o >>= 1) s += __shfl_xor_sync(0xffffffffu, s, o);
        p[e] = s;
    }

    if (lane == 0) {
        float mx = p[0];
#pragma unroll
        for (int e = 1; e < E_; e++) mx = fmaxf(mx, p[e]);
        float sum = 0.0f;
#pragma unroll
        for (int e = 0; e < E_; e++) { p[e] = expf(p[e] - mx); sum += p[e]; }
        float inv = 1.0f / sum;
#pragma unroll
        for (int e = 0; e < E_; e++) {
            p[e] *= inv;
            g_probs[(size_t)token * E_ + e] = p[e];
        }
        int i1 = 0;
#pragma unroll
        for (int e = 1; e < E_; e++) if (p[e] > p[i1]) i1 = e;
        int i2 = (i1 == 0) ? 1 : 0;
#pragma unroll
        for (int e = 0; e < E_; e++) if (e != i1 && p[e] > p[i2]) i2 = e;
        float s2 = p[i1] + p[i2];
        float w1 = p[i1] / s2, w2 = p[i2] / s2;

        int pos = atomicAdd(&g_cnt[i1], 1);
        g_tok[i1 * MAXPE + pos] = token; g_wt[i1 * MAXPE + pos] = w1;
        pos = atomicAdd(&g_cnt[i2], 1);
        g_tok[i2 * MAXPE + pos] = token; g_wt[i2 * MAXPE + pos] = w2;
    }
}

// ---------------- kernel 2: deterministic column-sum of probs ----------------
__global__ void reduce_probs_kernel(int N) {
    __shared__ float sm[256];
    int e = blockIdx.x;
    float s = 0.0f;
    for (int i = threadIdx.x; i < N; i += 256) s += g_probs[(size_t)i * E_ + e];
    sm[threadIdx.x] = s;
    __syncthreads();
    for (int o = 128; o; o >>= 1) {
        if (threadIdx.x < o) sm[threadIdx.x] += sm[threadIdx.x + o];
        __syncthreads();
    }
    if (threadIdx.x == 0) g_sumprob[e] = sm[0];
}

// ---------------- grouped GEMM: mma.sync bf16x3, cp.async 3-stage ----------------
// Block tile 128x256x32; warp grid 2x4, warp tile 64x64 (fixes LDSM:MMA ratio).
// Stage (48KB): A_hi[128 rows x 64B] @0, A_lo @8192, B_hi[256 x 64B] @16384,
// B_lo @32768. Chunk c of row r stored at 16B slot (c ^ ((r>>1)&3)).
// B fragments loaded per-g inside the MMA loop to cap register pressure.
// MODE 0: h = relu(x_planes @ wfc_planes^T)^2 -> g_h hi/lo planes (Kdim = D_)
// MODE 1: out += wt * (g_h planes @ wproj planes^T)  (atomicAdd) (Kdim = H_)
#define STAGE_BYTES 49152u
#define NSTAGE      3
#define SMEM_TOTAL  (NSTAGE * STAGE_BYTES)

template <int MODE>
__global__ __launch_bounds__(256, 1) void moe_gemm_mma(const u16* __restrict__ Ahi,
                                                       const u16* __restrict__ Alo,
                                                       const u16* __restrict__ Bhi,
                                                       const u16* __restrict__ Blo,
                                                       float* __restrict__ out,
                                                       int Kdim) {
    const int e   = blockIdx.z;
    const int cnt = g_cnt[e];
    const int m0  = blockIdx.y * BM;
    if (m0 >= cnt) return;
    const int n0 = blockIdx.x * BN;

    extern __shared__ __align__(128) char smem[];
    const uint32_t sb = smem_u32(smem);

    const int tid  = threadIdx.x;
    const int warp = tid >> 5, lane = tid & 31;
    const int wm = warp >> 2, wn = warp & 3;  // 2 x 4 warp grid, warp tile 64x64

    // ---- A loader: 2 threads per row, 2 chunks hi + 2 lo ----
    const int lrow  = tid >> 1;
    const int lhalf = tid & 1;
    const u16 *a_hi, *a_lo;
    if (MODE == 0) {
        int m   = m0 + lrow;
        int tok = g_tok[e * MAXPE + ((m < cnt) ? m : m0)];
        a_hi = Ahi + (size_t)tok * D_ + lhalf * 16;
        a_lo = Alo + (size_t)tok * D_ + lhalf * 16;
    } else {
        size_t off = ((size_t)(e * MAXPE + m0 + lrow)) * H_ + lhalf * 16;
        a_hi = Ahi + off;
        a_lo = Alo + off;
    }
    // ---- B loader: 1 thread per row, 4 chunks hi + 4 lo ----
    const size_t boff =
        (size_t)e * ((size_t)H_ * D_) + (size_t)(n0 + tid) * Kdim;
    const u16* b_hi = Bhi + boff;
    const u16* b_lo = Blo + boff;

    // swizzled dst offsets
    const uint32_t lswa  = (uint32_t)((lrow >> 1) & 3);
    const uint32_t st_a0 = (uint32_t)lrow * 64u + (((uint32_t)(lhalf * 2) ^ lswa) * 16u);
    const uint32_t st_a1 = (uint32_t)lrow * 64u + (((uint32_t)(lhalf * 2 + 1) ^ lswa) * 16u);
    const uint32_t lswb = (uint32_t)((tid >> 1) & 3);
    uint32_t st_b[4];
#pragma unroll
    for (int c = 0; c < 4; c++)
        st_b[c] = (uint32_t)tid * 64u + (((uint32_t)c ^ lswb) * 16u);

    // ---- ldmatrix per-lane swizzled addressing ----
    const int      row_a = wm * 64 + (lane & 15);
    const uint32_t sw_a  = (uint32_t)((row_a >> 1) & 3);
    const uint32_t a_row = (uint32_t)row_a * 64u;
    const uint32_t ca    = (uint32_t)(lane >> 4);
    const int      row_b = wn * 64 + ((lane >> 4) & 1) * 8 + (lane & 7);
    const uint32_t sw_b  = (uint32_t)((row_b >> 1) & 3);
    const uint32_t b_row = (uint32_t)row_b * 64u;
    const uint32_t cb    = (uint32_t)((lane >> 3) & 1);

    float acc[128];
#pragma unroll
    for (int i = 0; i < 128; i++) acc[i] = 0.0f;

    const int nk = Kdim / BK;

    // stage loader: 12 x cp.async(16B) per thread (A 4, B 8)
    auto load_stage = [&](int kt, int slot) {
        const uint32_t base = sb + (uint32_t)slot * STAGE_BYTES;
        const int koff = kt * BK;
        cpa16(base + st_a0, a_hi + koff);
        cpa16(base + st_a1, a_hi + koff + 8);
        cpa16(base + 8192 + st_a0, a_lo + koff);
        cpa16(base + 8192 + st_a1, a_lo + koff + 8);
#pragma unroll
        for (int c = 0; c < 4; c++) {
            cpa16(base + 16384 + st_b[c], b_hi + koff + c * 8);
            cpa16(base + 32768 + st_b[c], b_lo + koff + c * 8);
        }
    };

    // prologue: fill stages 0 and 1
    load_stage(0, 0);
    cp_commit();
    if (nk > 1) load_stage(1, 1);
    cp_commit();

    int slot = 0, nslot;
    for (int kt = 0; kt < nk; ++kt) {
        cp_wait1();
        __syncthreads();
        if (kt + 2 < nk) {
            int s2 = slot + 2;
            if (s2 >= NSTAGE) s2 -= NSTAGE;
            load_stage(kt + 2, s2);
        }
        cp_commit();

        const uint32_t base = sb + (uint32_t)slot * STAGE_BYTES;
#pragma unroll
        for (int ks = 0; ks < 2; ks++) {
            uint32_t ah[4][4], al[4][4];
            const uint32_t aoff = base + a_row + ((((uint32_t)(ks * 2) + ca) ^ sw_a) * 16u);
            const uint32_t boff2 =
                base + 16384 + b_row + ((((uint32_t)(ks * 2) + cb) ^ sw_b) * 16u);
#pragma unroll
            for (int am = 0; am < 4; am++) {
                ldsm4(ah[am], aoff + am * 1024);
                ldsm4(al[am], aoff + 8192 + am * 1024);
            }
#pragma unroll
            for (int g = 0; g < 4; g++) {
                uint32_t bh[4], bl[4];
                ldsm4(bh, boff2 + g * 1024);
                ldsm4(bl, boff2 + 16384 + g * 1024);
#pragma unroll
                for (int am = 0; am < 4; am++) {
                    float* c0 = &acc[(am * 8 + g * 2) * 4];
                    float* c1 = &acc[(am * 8 + g * 2 + 1) * 4];
                    mma_bf16(c0, ah[am], bh[0], bh[1]);
                    mma_bf16(c1, ah[am], bh[2], bh[3]);
                    mma_bf16(c0, ah[am], bl[0], bl[1]);
                    mma_bf16(c1, ah[am], bl[2], bl[3]);
                    mma_bf16(c0, al[am], bh[0], bh[1]);
                    mma_bf16(c1, al[am], bh[2], bh[3]);
                }
            }
        }
        slot = (slot + 1 == NSTAGE) ? 0 : slot + 1;
    }

    // ---- epilogue ----
    const int qr = lane >> 2;            // row within 8
    const int qc = (lane & 3) * 2;       // col pair within 8
    if (MODE == 0) {
#pragma unroll
        for (int am = 0; am < 4; am++)
#pragma unroll
            for (int hh = 0; hh < 2; hh++) {
                const int m = m0 + wm * 64 + am * 16 + qr + hh * 8;
                if (m >= cnt) continue;
                const size_t rowoff =
                    ((size_t)(e * MAXPE + m)) * H_ + n0 + wn * 64;
#pragma unroll
                for (int an = 0; an < 8; an++) {
                    const float* c = &acc[(am * 8 + an) * 4 + hh * 2];
                    float t0 = fmaxf(c[0], 0.f), t1 = fmaxf(c[1], 0.f);
                    float v0 = t0 * t0, v1 = t1 * t1;
                    uint32_t h, l;
                    split2(v0, v1, h, l);
                    const size_t off = rowoff + an * 8 + qc;
                    *(uint32_t*)(g_hhi + off) = h;
                    *(uint32_t*)(g_hlo + off) = l;
                }
            }
    } else {
#pragma unroll
        for (int am = 0; am < 4; am++)
#pragma unroll
            for (int hh = 0; hh < 2; hh++) {
                const int m = m0 + wm * 64 + am * 16 + qr + hh * 8;
                if (m >= cnt) continue;
                const int tok = g_tok[e * MAXPE + m];
                const float wt = g_wt[e * MAXPE + m];
                float* orow = out + (size_t)tok * D_ + n0 + wn * 64;
#pragma unroll
                for (int an = 0; an < 8; an++) {
                    const float* c = &acc[(am * 8 + an) * 4 + hh * 2];
                    atomicAdd(orow + an * 8 + qc, wt * c[0]);
                    atomicAdd(orow + an * 8 + qc + 1, wt * c[1]);
                }
            }
    }
}

// ---------------- loss ----------------
__global__ void loss_kernel(float* __restrict__ out, int N, int out_size) {
    if (out_size <= N * D_) return;
    float loss = 0.0f;
    for (int e = 0; e < E_; e++)
        loss += (g_sumprob[e] / (float)N) * ((float)g_cnt[e] / (float)N);
    out[(size_t)N * D_] = loss * (float)E_;
}

// ---------------- launch ----------------
extern "C" void kernel_launch(void* const* d_in, const int* in_sizes, int n_in,
                              void* d_out, int out_size) {
    const float* x     = (const float*)d_in[0];
    const float* gw    = (const float*)d_in[1];
    const float* wfc   = (const float*)d_in[2];
    const float* wproj = (const float*)d_in[3];
    float* out = (float*)d_out;
    int N = in_sizes[0] / D_;  // 4096

    cudaFuncSetAttribute(moe_gemm_mma<0>, cudaFuncAttributeMaxDynamicSharedMemorySize,
                         SMEM_TOTAL);
    cudaFuncSetAttribute(moe_gemm_mma<1>, cudaFuncAttributeMaxDynamicSharedMemorySize,
                         SMEM_TOTAL);

    // resolve device-global plane addresses (host-side)
    u16 *xhi, *xlo, *wfchi, *wfclo, *wprohi, *wprolo;
    cudaGetSymbolAddress((void**)&xhi, g_xhi);
    cudaGetSymbolAddress((void**)&xlo, g_xlo);
    cudaGetSymbolAddress((void**)&wfchi, g_wfchi);
    cudaGetSymbolAddress((void**)&wfclo, g_wfclo);
    cudaGetSymbolAddress((void**)&wprohi, g_wprohi);
    cudaGetSymbolAddress((void**)&wprolo, g_wprolo);
    u16 *hhi, *hlo;
    cudaGetSymbolAddress((void**)&hhi, g_hhi);
    cudaGetSymbolAddress((void**)&hlo, g_hlo);

    zero_kernel<<<1024, 256>>>(out, out_size);
    cvt_kernel<<<2048, 256>>>(x, xhi, xlo, N * D_ / 4);
    cvt_kernel<<<2048, 256>>>(wfc, wfchi, wfclo, E_ * H_ * D_ / 4);
    cvt_kernel<<<2048, 256>>>(wproj, wprohi, wprolo, E_ * D_ * H_ / 4);
    gate_kernel<<<(N + 7) / 8, 256>>>(x, gw, N);
    reduce_probs_kernel<<<E_, 256>>>(N);

    // x = N-tiles fast-varying (A-tile L2 reuse), y = M-tiles, z = expert
    dim3 g1(H_ / BN, MAXPE / BM, E_);
    moe_gemm_mma<0><<<g1, 256, SMEM_TOTAL>>>(xhi, xlo, wfchi, wfclo, nullptr, D_);

    dim3 g2(D_ / BN, MAXPE / BM, E_);
    moe_gemm_mma<1><<<g2, 256, SMEM_TOTAL>>>(hhi, hlo, wprohi, wprolo, out, H_);

    loss_kernel<<<1, 1>>>(out, N, out_size);
}

// round 12
// speedup vs baseline: 1.4600x; 1.4600x over previous
#include <cuda_runtime.h>
#include <cuda_bf16.h>
#include <cstdint>

// ---------------- problem constants ----------------
#define D_    768
#define H_    3072
#define E_    8
#define MAXPE 4096
#define NMAX  4096

#define BM 128
#define BN 128
#define BK 32

typedef unsigned short u16;

// ---------------- device scratch (bf16 hi/lo planes) ----------------
__device__ u16   g_xhi[(size_t)NMAX * D_];
__device__ u16   g_xlo[(size_t)NMAX * D_];
__device__ u16   g_wfchi[(size_t)E_ * H_ * D_];
__device__ u16   g_wfclo[(size_t)E_ * H_ * D_];
__device__ u16   g_wprohi[(size_t)E_ * D_ * H_];
__device__ u16   g_wprolo[(size_t)E_ * D_ * H_];
__device__ u16   g_hhi[(size_t)E_ * MAXPE * H_];
__device__ u16   g_hlo[(size_t)E_ * MAXPE * H_];
__device__ int   g_tok[E_ * MAXPE];
__device__ float g_wt[E_ * MAXPE];
__device__ float g_probs[(size_t)NMAX * E_];
__device__ int   g_cnt[E_];
__device__ float g_sumprob[E_];

// ---------------- helpers ----------------
__device__ __forceinline__ uint32_t smem_u32(const void* p) {
    uint32_t a;
    asm("{ .reg .u64 t; cvta.to.shared.u64 t, %1; cvt.u32.u64 %0, t; }" : "=r"(a) : "l"(p));
    return a;
}
__device__ __forceinline__ void ldsm4(uint32_t* r, uint32_t addr) {
    asm volatile("ldmatrix.sync.aligned.m8n8.x4.shared.b16 {%0,%1,%2,%3}, [%4];"
                 : "=r"(r[0]), "=r"(r[1]), "=r"(r[2]), "=r"(r[3]) : "r"(addr));
}
__device__ __forceinline__ void mma_bf16(float* c, const uint32_t* a, uint32_t b0, uint32_t b1) {
    asm volatile("mma.sync.aligned.m16n8k16.row.col.f32.bf16.bf16.f32 "
                 "{%0,%1,%2,%3}, {%4,%5,%6,%7}, {%8,%9}, {%0,%1,%2,%3};"
                 : "+f"(c[0]), "+f"(c[1]), "+f"(c[2]), "+f"(c[3])
                 : "r"(a[0]), "r"(a[1]), "r"(a[2]), "r"(a[3]), "r"(b0), "r"(b1));
}
__device__ __forceinline__ void cpa16(uint32_t dst, const void* src) {
    asm volatile("cp.async.cg.shared.global [%0], [%1], 16;" :: "r"(dst), "l"(src));
}
__device__ __forceinline__ void cp_commit() {
    asm volatile("cp.async.commit_group;" ::: "memory");
}
__device__ __forceinline__ void cp_wait1() {
    asm volatile("cp.async.wait_group 1;" ::: "memory");
}
// split two floats -> hi bf16x2 (packed) and lo bf16x2 (packed)
__device__ __forceinline__ void split2(float x, float y, uint32_t& h, uint32_t& l) {
    __nv_bfloat162 a = __floats2bfloat162_rn(x, y);
    h = *reinterpret_cast<uint32_t*>(&a);
    float f0 = __uint_as_float(h << 16);
    float f1 = __uint_as_float(h & 0xffff0000u);
    __nv_bfloat162 b = __floats2bfloat162_rn(x - f0, y - f1);
    l = *reinterpret_cast<uint32_t*>(&b);
}

// ---------------- kernel: fp32 -> bf16 hi/lo planes ----------------
__global__ void cvt_kernel(const float* __restrict__ src, u16* __restrict__ hi,
                           u16* __restrict__ lo, int n4) {
    for (int i = blockIdx.x * blockDim.x + threadIdx.x; i < n4;
         i += gridDim.x * blockDim.x) {
        float4 v = ((const float4*)src)[i];
        uint32_t h0, h1, l0, l1;
        split2(v.x, v.y, h0, l0);
        split2(v.z, v.w, h1, l1);
        ((uint2*)hi)[i] = make_uint2(h0, h1);
        ((uint2*)lo)[i] = make_uint2(l0, l1);
    }
}

// ---------------- kernel 0: zero output + counters ----------------
__global__ void zero_kernel(float* __restrict__ out, int out_size) {
    for (int i = blockIdx.x * blockDim.x + threadIdx.x; i < out_size;
         i += gridDim.x * blockDim.x)
        out[i] = 0.0f;
    if (blockIdx.x == 0 && threadIdx.x < E_) g_cnt[threadIdx.x] = 0;
}

// ---------------- kernel 1: gating ----------------
__global__ __launch_bounds__(256) void gate_kernel(const float* __restrict__ x,
                                                   const float* __restrict__ gw,
                                                   int N) {
    int token = blockIdx.x * 8 + (threadIdx.x >> 5);
    int lane  = threadIdx.x & 31;
    if (token >= N) return;

    const float* xr = x + (size_t)token * D_;
    float xs[D_ / 32];
#pragma unroll
    for (int i = 0; i < D_ / 32; i++) xs[i] = xr[lane + i * 32];

    float p[E_];
#pragma unroll
    for (int e = 0; e < E_; e++) {
        const float* g = gw + e * D_;
        float s = 0.0f;
#pragma unroll
        for (int i = 0; i < D_ / 32; i++) s += xs[i] * g[lane + i * 32];
#pragma unroll
        for (int o = 16; o; o >>= 1) s += __shfl_xor_sync(0xffffffffu, s, o);
        p[e] = s;
    }

    if (lane == 0) {
        float mx = p[0];
#pragma unroll
        for (int e = 1; e < E_; e++) mx = fmaxf(mx, p[e]);
        float sum = 0.0f;
#pragma unroll
        for (int e = 0; e < E_; e++) { p[e] = expf(p[e] - mx); sum += p[e]; }
        float inv = 1.0f / sum;
#pragma unroll
        for (int e = 0; e < E_; e++) {
            p[e] *= inv;
            g_probs[(size_t)token * E_ + e] = p[e];
        }
        int i1 = 0;
#pragma unroll
        for (int e = 1; e < E_; e++) if (p[e] > p[i1]) i1 = e;
        int i2 = (i1 == 0) ? 1 : 0;
#pragma unroll
        for (int e = 0; e < E_; e++) if (e != i1 && p[e] > p[i2]) i2 = e;
        float s2 = p[i1] + p[i2];
        float w1 = p[i1] / s2, w2 = p[i2] / s2;

        int pos = atomicAdd(&g_cnt[i1], 1);
        g_tok[i1 * MAXPE + pos] = token; g_wt[i1 * MAXPE + pos] = w1;
        pos = atomicAdd(&g_cnt[i2], 1);
        g_tok[i2 * MAXPE + pos] = token; g_wt[i2 * MAXPE + pos] = w2;
    }
}

// ---------------- kernel 2: deterministic column-sum of probs ----------------
__global__ void reduce_probs_kernel(int N) {
    __shared__ float sm[256];
    int e = blockIdx.x;
    float s = 0.0f;
    for (int i = threadIdx.x; i < N; i += 256) s += g_probs[(size_t)i * E_ + e];
    sm[threadIdx.x] = s;
    __syncthreads();
    for (int o = 128; o; o >>= 1) {
        if (threadIdx.x < o) sm[threadIdx.x] += sm[threadIdx.x + o];
        __syncthreads();
    }
    if (threadIdx.x == 0) g_sumprob[e] = sm[0];
}

// ---------------- grouped GEMM: mma.sync bf16x3, cp.async 3-stage, 2 CTA/SM ----
// Block tile 128x128x32; warp grid 2x4, warp tile 64x32; 64 accumulators.
// __launch_bounds__(256, 2) caps regs at 128 so TWO CTAs co-reside per SM
// (2 x 96KB smem = 192KB <= 227KB) -> 4 warps/SMSP for latency hiding.
// Stage (32KB): A_hi[128 rows x 64B] @0, A_lo @8192, B_hi @16384, B_lo @24576.
// Chunk c of row r stored at 16B slot (c ^ ((r>>1)&3)) -> conflict-free.
// MODE 0: h = relu(x_planes @ wfc_planes^T)^2 -> g_h hi/lo planes (Kdim = D_)
// MODE 1: out += wt * (g_h planes @ wproj planes^T)  (atomicAdd) (Kdim = H_)
#define STAGE_BYTES 32768u
#define NSTAGE      3
#define SMEM_TOTAL  (NSTAGE * STAGE_BYTES)

template <int MODE>
__global__ __launch_bounds__(256, 2) void moe_gemm_mma(const u16* __restrict__ Ahi,
                                                       const u16* __restrict__ Alo,
                                                       const u16* __restrict__ Bhi,
                                                       const u16* __restrict__ Blo,
                                                       float* __restrict__ out,
                                                       int Kdim) {
    const int e   = blockIdx.z;
    const int cnt = g_cnt[e];
    const int m0  = blockIdx.y * BM;
    if (m0 >= cnt) return;
    const int n0 = blockIdx.x * BN;

    extern __shared__ __align__(128) char smem[];
    const uint32_t sb = smem_u32(smem);

    const int tid  = threadIdx.x;
    const int warp = tid >> 5, lane = tid & 31;
    const int wm = warp >> 2, wn = warp & 3;  // 2 x 4 warp grid, warp tile 64x32

    // ---- loader mapping: 2 threads per row, 2 chunks of 16B each plane ----
    const int lrow  = tid >> 1;
    const int lhalf = tid & 1;
    const u16 *a_hi, *a_lo;
    if (MODE == 0) {
        int m   = m0 + lrow;
        int tok = g_tok[e * MAXPE + ((m < cnt) ? m : m0)];
        a_hi = Ahi + (size_t)tok * D_ + lhalf * 16;
        a_lo = Alo + (size_t)tok * D_ + lhalf * 16;
    } else {
        size_t off = ((size_t)(e * MAXPE + m0 + lrow)) * H_ + lhalf * 16;
        a_hi = Ahi + off;
        a_lo = Alo + off;
    }
    const size_t boff = (size_t)e * ((size_t)H_ * D_) + (size_t)(n0 + lrow) * Kdim +
                        (size_t)(lhalf * 16);
    const u16* b_hi = Bhi + boff;
    const u16* b_lo = Blo + boff;

    // swizzled dst offsets for the 2 chunks (c = lhalf*2, lhalf*2+1)
    const uint32_t lsw   = (uint32_t)((lrow >> 1) & 3);
    const uint32_t st_c0 = (uint32_t)lrow * 64u + (((uint32_t)(lhalf * 2) ^ lsw) * 16u);
    const uint32_t st_c1 = (uint32_t)lrow * 64u + (((uint32_t)(lhalf * 2 + 1) ^ lsw) * 16u);

    // ---- ldmatrix per-lane swizzled addressing ----
    const int      row_a = wm * 64 + (lane & 15);
    const uint32_t sw_a  = (uint32_t)((row_a >> 1) & 3);
    const uint32_t a_row = (uint32_t)row_a * 64u;
    const uint32_t ca    = (uint32_t)(lane >> 4);
    const int      row_b = wn * 32 + ((lane >> 4) & 1) * 8 + (lane & 7);
    const uint32_t sw_b  = (uint32_t)((row_b >> 1) & 3);
    const uint32_t b_row = (uint32_t)row_b * 64u;
    const uint32_t cb    = (uint32_t)((lane >> 3) & 1);

    float acc[64];
#pragma unroll
    for (int i = 0; i < 64; i++) acc[i] = 0.0f;

    const int nk = Kdim / BK;

    // stage loader: 8 x cp.async(16B) per thread
    auto load_stage = [&](int kt, int slot) {
        const uint32_t base = sb + (uint32_t)slot * STAGE_BYTES;
        const int koff = kt * BK;
        cpa16(base + st_c0, a_hi + koff);
        cpa16(base + st_c1, a_hi + koff + 8);
        cpa16(base + 8192 + st_c0, a_lo + koff);
        cpa16(base + 8192 + st_c1, a_lo + koff + 8);
        cpa16(base + 16384 + st_c0, b_hi + koff);
        cpa16(base + 16384 + st_c1, b_hi + koff + 8);
        cpa16(base + 24576 + st_c0, b_lo + koff);
        cpa16(base + 24576 + st_c1, b_lo + koff + 8);
    };

    // prologue: fill stages 0 and 1
    load_stage(0, 0);
    cp_commit();
    if (nk > 1) load_stage(1, 1);
    cp_commit();

    int slot = 0;
    for (int kt = 0; kt < nk; ++kt) {
        cp_wait1();
        __syncthreads();
        if (kt + 2 < nk) {
            int s2 = slot + 2;
            if (s2 >= NSTAGE) s2 -= NSTAGE;
            load_stage(kt + 2, s2);
        }
        cp_commit();

        const uint32_t base = sb + (uint32_t)slot * STAGE_BYTES;
#pragma unroll
        for (int ks = 0; ks < 2; ks++) {
            uint32_t ah[4][4], al[4][4];
            const uint32_t aoff = base + a_row + ((((uint32_t)(ks * 2) + ca) ^ sw_a) * 16u);
            const uint32_t boff2 =
                base + 16384 + b_row + ((((uint32_t)(ks * 2) + cb) ^ sw_b) * 16u);
#pragma unroll
            for (int am = 0; am < 4; am++) {
                ldsm4(ah[am], aoff + am * 1024);
                ldsm4(al[am], aoff + 8192 + am * 1024);
            }
#pragma unroll
            for (int g = 0; g < 2; g++) {
                uint32_t bh[4], bl[4];
                ldsm4(bh, boff2 + g * 1024);
                ldsm4(bl, boff2 + 8192 + g * 1024);
#pragma unroll
                for (int am = 0; am < 4; am++) {
                    float* c0 = &acc[(am * 4 + g * 2) * 4];
                    float* c1 = &acc[(am * 4 + g * 2 + 1) * 4];
                    mma_bf16(c0, ah[am], bh[0], bh[1]);
                    mma_bf16(c1, ah[am], bh[2], bh[3]);
                    mma_bf16(c0, ah[am], bl[0], bl[1]);
                    mma_bf16(c1, ah[am], bl[2], bl[3]);
                    mma_bf16(c0, al[am], bh[0], bh[1]);
                    mma_bf16(c1, al[am], bh[2], bh[3]);
                }
            }
        }
        slot = (slot + 1 == NSTAGE) ? 0 : slot + 1;
    }

    // ---- epilogue ----
    const int qr = lane >> 2;            // row within 8
    const int qc = (lane & 3) * 2;       // col pair within 8
    if (MODE == 0) {
#pragma unroll
        for (int am = 0; am < 4; am++)
#pragma unroll
            for (int hh = 0; hh < 2; hh++) {
                const int m = m0 + wm * 64 + am * 16 + qr + hh * 8;
                if (m >= cnt) continue;
                const size_t rowoff =
                    ((size_t)(e * MAXPE + m)) * H_ + n0 + wn * 32;
#pragma unroll
                for (int an = 0; an < 4; an++) {
                    const float* c = &acc[(am * 4 + an) * 4 + hh * 2];
                    float t0 = fmaxf(c[0], 0.f), t1 = fmaxf(c[1], 0.f);
                    float v0 = t0 * t0, v1 = t1 * t1;
                    uint32_t h, l;
                    split2(v0, v1, h, l);
                    const size_t off = rowoff + an * 8 + qc;
                    *(uint32_t*)(g_hhi + off) = h;
                    *(uint32_t*)(g_hlo + off) = l;
                }
            }
    } else {
#pragma unroll
        for (int am = 0; am < 4; am++)
#pragma unroll
            for (int hh = 0; hh < 2; hh++) {
                const int m = m0 + wm * 64 + am * 16 + qr + hh * 8;
                if (m >= cnt) continue;
                const int tok = g_tok[e * MAXPE + m];
                const float wt = g_wt[e * MAXPE + m];
                float* orow = out + (size_t)tok * D_ + n0 + wn * 32;
#pragma unroll
                for (int an = 0; an < 4; an++) {
                    const float* c = &acc[(am * 4 + an) * 4 + hh * 2];
                    atomicAdd(orow + an * 8 + qc, wt * c[0]);
                    atomicAdd(orow + an * 8 + qc + 1, wt * c[1]);
                }
            }
    }
}

// ---------------- loss ----------------
__global__ void loss_kernel(float* __restrict__ out, int N, int out_size) {
    if (out_size <= N * D_) return;
    float loss = 0.0f;
    for (int e = 0; e < E_; e++)
        loss += (g_sumprob[e] / (float)N) * ((float)g_cnt[e] / (float)N);
    out[(size_t)N * D_] = loss * (float)E_;
}

// ---------------- launch ----------------
extern "C" void kernel_launch(void* const* d_in, const int* in_sizes, int n_in,
                              void* d_out, int out_size) {
    const float* x     = (const float*)d_in[0];
    const float* gw    = (const float*)d_in[1];
    const float* wfc   = (const float*)d_in[2];
    const float* wproj = (const float*)d_in[3];
    float* out = (float*)d_out;
    int N = in_sizes[0] / D_;  // 4096

    cudaFuncSetAttribute(moe_gemm_mma<0>, cudaFuncAttributeMaxDynamicSharedMemorySize,
                         SMEM_TOTAL);
    cudaFuncSetAttribute(moe_gemm_mma<1>, cudaFuncAttributeMaxDynamicSharedMemorySize,
                         SMEM_TOTAL);

    // resolve device-global plane addresses (host-side)
    u16 *xhi, *xlo, *wfchi, *wfclo, *wprohi, *wprolo;
    cudaGetSymbolAddress((void**)&xhi, g_xhi);
    cudaGetSymbolAddress((void**)&xlo, g_xlo);
    cudaGetSymbolAddress((void**)&wfchi, g_wfchi);
    cudaGetSymbolAddress((void**)&wfclo, g_wfclo);
    cudaGetSymbolAddress((void**)&wprohi, g_wprohi);
    cudaGetSymbolAddress((void**)&wprolo, g_wprolo);
    u16 *hhi, *hlo;
    cudaGetSymbolAddress((void**)&hhi, g_hhi);
    cudaGetSymbolAddress((void**)&hlo, g_hlo);

    zero_kernel<<<1024, 256>>>(out, out_size);
    cvt_kernel<<<2048, 256>>>(x, xhi, xlo, N * D_ / 4);
    cvt_kernel<<<2048, 256>>>(wfc, wfchi, wfclo, E_ * H_ * D_ / 4);
    cvt_kernel<<<2048, 256>>>(wproj, wprohi, wprolo, E_ * D_ * H_ / 4);
    gate_kernel<<<(N + 7) / 8, 256>>>(x, gw, N);
    reduce_probs_kernel<<<E_, 256>>>(N);

    // x = N-tiles fast-varying (A-tile L2 reuse), y = M-tiles, z = expert
    dim3 g1(H_ / BN, MAXPE / BM, E_);
    moe_gemm_mma<0><<<g1, 256, SMEM_TOTAL>>>(xhi, xlo, wfchi, wfclo, nullptr, D_);

    dim3 g2(D_ / BN, MAXPE / BM, E_);
    moe_gemm_mma<1><<<g2, 256, SMEM_TOTAL>>>(hhi, hlo, wprohi, wprolo, out, H_);

    loss_kernel<<<1, 1>>>(out, N, out_size);
}